// round 17
// baseline (speedup 1.0000x reference)
#include <cuda_runtime.h>
#include <cuda_bf16.h>
#include <cuda_fp16.h>
#include <cstdint>

#define NN 50000
#define NP 50048          // padded rows (multiple of 128) for unguarded cp.async
#define EE 800000
#define HD 256
#define DESW 768
#define NSEG (2 * NN)
#define SCAN_B ((NSEG + 1023) / 1024)   // 98 scan blocks

// ---------------- scratch (device globals; no runtime alloc) ----------------
__device__ __align__(16) __half g_x[(size_t)2 * NP * HD];      // fp16 activations, 2 slots
__device__ __align__(16) __half g_hrel[(size_t)2 * NN * HD];   // fp16 messages
__device__ __align__(16) __half g_hroot[(size_t)NN * HD];      // fp16 root
__device__ __align__(16) int   g_cnt[NSEG];
__device__ __align__(16) int   g_off[NSEG + 1];
__device__ __align__(16) int   g_cursor[NSEG];
__device__ __align__(16) int   g_eidx[EE];
__device__ __align__(16) int   g_bsum[128];
__device__ __align__(16) int   g_bpre[128];

#define OFF_DES 0
#define OFF_TW  49152
#define OFF_WIN 98304
#define OFF_R1  163840
#define OFF_R2  360448
__device__ __align__(16) __half g_w[557056];     // fp16 weights, transposed [N,K]

// ---------------- helpers -----------------------------------------------------
__device__ __forceinline__ uint32_t smem_u32(const void* p) {
    uint32_t a;
    asm("{ .reg .u64 t; cvta.to.shared.u64 t, %1; cvt.u32.u64 %0, t; }" : "=r"(a) : "l"(p));
    return a;
}
__device__ __forceinline__ void ldsm4(uint32_t* r, uint32_t addr) {
    asm volatile("ldmatrix.sync.aligned.m8n8.x4.shared.b16 {%0,%1,%2,%3}, [%4];"
                 : "=r"(r[0]), "=r"(r[1]), "=r"(r[2]), "=r"(r[3]) : "r"(addr));
}
__device__ __forceinline__ void mma_f16(float* c, const uint32_t* a, const uint32_t* b) {
    asm volatile(
        "mma.sync.aligned.m16n8k16.row.col.f32.f16.f16.f32 "
        "{%0,%1,%2,%3}, {%4,%5,%6,%7}, {%8,%9}, {%0,%1,%2,%3};"
        : "+f"(c[0]), "+f"(c[1]), "+f"(c[2]), "+f"(c[3])
        : "r"(a[0]), "r"(a[1]), "r"(a[2]), "r"(a[3]), "r"(b[0]), "r"(b[1]));
}
__device__ __forceinline__ void cpa16(uint32_t dst, const void* src) {
    asm volatile("cp.async.cg.shared.global [%0], [%1], 16;" :: "r"(dst), "l"(src));
}
__device__ __forceinline__ void cp_commit() {
    asm volatile("cp.async.commit_group;" ::: "memory");
}
template <int N>
__device__ __forceinline__ void cp_wait() {
    asm volatile("cp.async.wait_group %0;" :: "n"(N) : "memory");
}
__device__ __forceinline__ float actf(float v, int act) {
    if (act == 1) return v > 0.f ? v : 0.01f * v;
    if (act == 2) return v > 0.f ? v : 0.f;
    return v;
}
// 8 fp32 -> 8 fp16 packed in uint4
__device__ __forceinline__ uint4 cvt8h(float4 x, float4 y) {
    uint4 r;
    *(__half2*)&r.x = __floats2half2_rn(x.x, x.y);
    *(__half2*)&r.y = __floats2half2_rn(x.z, x.w);
    *(__half2*)&r.z = __floats2half2_rn(y.x, y.y);
    *(__half2*)&r.w = __floats2half2_rn(y.z, y.w);
    return r;
}

// ---------------- weight prep (split: early 768 mats / rest) ------------------
__device__ __forceinline__ void wprep_one(const float* W, int K, int N, int off, int id) {
    if (id >= K * N) return;
    int k = id / N, n = id - k * N;
    g_w[(size_t)off + (size_t)n * K + k] = __float2half_rn(W[id]);
}
__global__ void k_wprep768(const float* __restrict__ w_des, const float* __restrict__ w_tw) {
    int id = blockIdx.x * blockDim.x + threadIdx.x;
    wprep_one(blockIdx.y ? w_tw : w_des, 768, 64, blockIdx.y ? OFF_TW : OFF_DES, id);
}
__global__ void k_wprep_rest(const float* __restrict__ w_in, const float* __restrict__ wt1,
                             const float* __restrict__ rt1, const float* __restrict__ wt2,
                             const float* __restrict__ rt2) {
    int id = blockIdx.x * blockDim.x + threadIdx.x;
    int y = blockIdx.y;
    const float* W;
    int off;
    switch (y) {
        case 0: W = w_in;          off = OFF_WIN;           break;
        case 1: W = wt1;           off = OFF_R1;            break;
        case 2: W = wt1 + 65536;   off = OFF_R1 + 65536;    break;
        case 3: W = rt1;           off = OFF_R1 + 131072;   break;
        case 4: W = wt2;           off = OFF_R2;            break;
        case 5: W = wt2 + 65536;   off = OFF_R2 + 65536;    break;
        default: W = rt2;          off = OFF_R2 + 131072;   break;
    }
    wprep_one(W, 256, 256, off, id);
}

// ---------------- cp.async double-buffered pure-fp16 GEMM ---------------------
template <int BN, int AMODE>
__global__ void __launch_bounds__(256) k_gemm_mma(
    const float* __restrict__ Ap0, const float* __restrict__ Ap1, int aSlot,
    int K, int M, int bOff,
    const float* __restrict__ bias0, const float* __restrict__ bias1,
    int cSel, int cbase, int cmode, int act)
{
    extern __shared__ char sm[];
    constexpr int STR = 144;
    constexpr int ABUF = 128 * STR;
    constexpr int BBUF = BN * STR;
    constexpr int NT = BN / 16;

    const uint32_t smb = smem_u32(sm);
    const int tid = threadIdx.x;
    const int lane = tid & 31, wid = tid >> 5;
    const int m_base = (wid & 3) * 32;
    const int n_base = (wid >> 2) * (BN / 2);

    const float* Aparam = (AMODE == 0 && blockIdx.x) ? Ap1 : Ap0;
    const float* bias = (AMODE == 0 && blockIdx.x) ? bias1 : bias0;
    const int cb = (AMODE == 0) ? (blockIdx.x ? cbase : 0) : cbase;
    const int boff_g = (AMODE == 0) ? (blockIdx.x ? OFF_TW : OFF_DES) : bOff;

    const __half* Ah = g_x + (size_t)aSlot * NP * HD;
    const __half* B = g_w + boff_g;

    const int m0 = blockIdx.y * 128;
    const int n0 = (AMODE == 0) ? 0 : blockIdx.x * BN;
    const int nch = K >> 6;

    const int lrow = tid >> 1, lhalf = tid & 1;

    float acc[2][NT][4];
#pragma unroll
    for (int i = 0; i < 2; i++)
#pragma unroll
        for (int j = 0; j < NT; j++)
#pragma unroll
            for (int q = 0; q < 4; q++) acc[i][j][q] = 0.f;

    const uint32_t aoff = (uint32_t)(m_base + (lane & 15)) * STR + (uint32_t)(lane >> 4) * 16;
    const uint32_t boff = (uint32_t)(n_base + ((lane >> 4) & 1) * 8 + (lane & 7)) * STR +
                          (uint32_t)((lane >> 3) & 1) * 16;

    float4 areg[8];
    auto load_regs = [&](int c) {
        if (AMODE == 0) {
            int gr = m0 + lrow;
            if (gr < M) {
                const float4* srcp = (const float4*)(Aparam + (size_t)gr * K + c * 64 + lhalf * 32);
#pragma unroll
                for (int j = 0; j < 8; j++) areg[j] = srcp[j];
            } else {
#pragma unroll
                for (int j = 0; j < 8; j++) areg[j] = make_float4(0.f, 0.f, 0.f, 0.f);
            }
        }
    };

    auto loadA = [&](int c, int buf) {
        if (AMODE == 1) {
            int k0 = c * 64;
            size_t base = (size_t)(m0 + lrow) * HD + k0 + lhalf * 32;
            uint32_t d = smb + buf * ABUF + lrow * STR + lhalf * 64;
#pragma unroll
            for (int j = 0; j < 4; j++)
                cpa16(d + j * 16, Ah + base + j * 8);
        }
    };
    auto loadB = [&](int c, int buf) {
        if (lrow < BN) {
            int k0 = c * 64;
            size_t base = (size_t)(n0 + lrow) * K + k0 + lhalf * 32;
            uint32_t d = smb + 2 * ABUF + buf * BBUF + lrow * STR + lhalf * 64;
#pragma unroll
            for (int j = 0; j < 4; j++)
                cpa16(d + j * 16, B + base + j * 8);
        }
    };

    loadA(0, 0);
    loadB(0, 0);
    cp_commit();
    load_regs(0);

    for (int c = 0; c < nch; c++) {
        const int buf = c & 1;
        if (c + 1 < nch) {
            loadA(c + 1, buf ^ 1);
            loadB(c + 1, buf ^ 1);
            cp_commit();
            cp_wait<1>();
        } else {
            cp_wait<0>();
        }
        __syncthreads();

        if (AMODE == 0) {
            uint4 h[4];
#pragma unroll
            for (int j = 0; j < 4; j++) h[j] = cvt8h(areg[2 * j], areg[2 * j + 1]);
#pragma unroll
            for (int j = 0; j < 4; j++)
                *(uint4*)(sm + buf * ABUF + lrow * STR + lhalf * 64 + j * 16) = h[j];
            if (c + 1 < nch) load_regs(c + 1);
            __syncthreads();
        }

        const uint32_t ab = smb + buf * ABUF;
        const uint32_t bb = smb + 2 * ABUF + buf * BBUF;

#pragma unroll
        for (int k16 = 0; k16 < 4; k16++) {
            uint32_t aH[2][4];
#pragma unroll
            for (int mi = 0; mi < 2; mi++)
                ldsm4(aH[mi], ab + aoff + mi * (16 * STR) + k16 * 32);
#pragma unroll
            for (int pr = 0; pr < NT / 2; pr++) {
                uint32_t bH[4];
                ldsm4(bH, bb + boff + pr * (16 * STR) + k16 * 32);
#pragma unroll
                for (int mi = 0; mi < 2; mi++)
#pragma unroll
                    for (int t = 0; t < 2; t++)
                        mma_f16(acc[mi][pr * 2 + t], aH[mi], bH + 2 * t);
            }
        }
        __syncthreads();
    }

    // ---- epilogue ----
#pragma unroll
    for (int mi = 0; mi < 2; mi++) {
#pragma unroll
        for (int nt = 0; nt < NT; nt++) {
            int colL = n_base + nt * 8 + (lane & 3) * 2;
            int gcolL = n0 + colL;
            int bidx = (cmode == 1) ? (gcolL & 255) : colL;
            float b0 = bias[bidx], b1 = bias[bidx + 1];
#pragma unroll
            for (int half = 0; half < 2; half++) {
                int gr = m0 + m_base + mi * 16 + (lane >> 2) + half * 8;
                if (gr < M) {
                    float vx = actf(acc[mi][nt][half * 2 + 0] + b0, act);
                    float vy = actf(acc[mi][nt][half * 2 + 1] + b1, act);
                    __half2 hv = __floats2half2_rn(vx, vy);
                    if (cmode == 1) {
                        int seg = gcolL >> 8, lc = gcolL & 255;
                        __half* dstp = (seg < 2)
                            ? g_hrel + ((size_t)seg * NN + gr) * 256 + lc
                            : g_hroot + (size_t)gr * 256 + lc;
                        *(__half2*)dstp = hv;
                    } else {
                        int slot = cSel - 1;
                        size_t eoff = (size_t)slot * NP * HD + (size_t)gr * HD + cb + gcolL;
                        *(__half2*)(g_x + eoff) = hv;
                    }
                }
            }
        }
    }
}

// ---------------- small projections (K=5 and K=3 merged) -> slot0 fp16 -------
__global__ void k_projsmall(const float* __restrict__ An, const float* __restrict__ Wn,
                            const float* __restrict__ bn,
                            const float* __restrict__ Ac, const float* __restrict__ Wc,
                            const float* __restrict__ bc)
{
    int id = blockIdx.x * blockDim.x + threadIdx.x;
    if (id >= NN * 64) return;
    int n = id >> 6, j = id & 63;
    const float* A = blockIdx.y ? Ac : An;
    const float* W = blockIdx.y ? Wc : Wn;
    const float* bias = blockIdx.y ? bc : bn;
    int K = blockIdx.y ? 3 : 5;
    int coloff = blockIdx.y ? 192 : 128;
    float s = bias[j];
    for (int k = 0; k < K; k++) s += A[(size_t)n * K + k] * W[k * 64 + j];
    s = actf(s, 1);
    g_x[(size_t)n * HD + coloff + j] = __float2half_rn(s);
}

// ---------------- CSR build ---------------------------------------------------
__global__ void k_zero_cnt() {
    int id = blockIdx.x * blockDim.x + threadIdx.x;
    if (id < NSEG) g_cnt[id] = 0;
}
__global__ void k_count(const int* __restrict__ dst, const int* __restrict__ et) {
    int e = blockIdx.x * blockDim.x + threadIdx.x;
    if (e >= EE) return;
    atomicAdd(&g_cnt[et[e] * NN + dst[e]], 1);
}
__global__ void k_scan1() {
    __shared__ int sh[1024];
    int idx = blockIdx.x * 1024 + threadIdx.x;
    int v = (idx < NSEG) ? g_cnt[idx] : 0;
    sh[threadIdx.x] = v;
    __syncthreads();
    for (int off = 1; off < 1024; off <<= 1) {
        int t = (threadIdx.x >= off) ? sh[threadIdx.x - off] : 0;
        __syncthreads();
        sh[threadIdx.x] += t;
        __syncthreads();
    }
    if (idx < NSEG) g_off[idx] = sh[threadIdx.x] - v;
    if (threadIdx.x == 1023) g_bsum[blockIdx.x] = sh[1023];
}
__global__ void k_scan2() {
    __shared__ int sh[128];
    int v = (threadIdx.x < SCAN_B) ? g_bsum[threadIdx.x] : 0;
    sh[threadIdx.x] = v;
    __syncthreads();
    for (int off = 1; off < 128; off <<= 1) {
        int t = (threadIdx.x >= off) ? sh[threadIdx.x - off] : 0;
        __syncthreads();
        sh[threadIdx.x] += t;
        __syncthreads();
    }
    if (threadIdx.x < SCAN_B) g_bpre[threadIdx.x] = sh[threadIdx.x] - v;
    if (threadIdx.x == 127) g_off[NSEG] = sh[127];
}
__global__ void k_scan3() {
    int idx = blockIdx.x * 1024 + threadIdx.x;
    if (idx < NSEG) {
        int o = g_off[idx] + g_bpre[blockIdx.x];
        g_off[idx] = o;
        g_cursor[idx] = o;
    }
}
__global__ void k_fill(const int* __restrict__ src, const int* __restrict__ dst,
                       const int* __restrict__ et) {
    int e = blockIdx.x * blockDim.x + threadIdx.x;
    if (e >= EE) return;
    int seg = et[e] * NN + dst[e];
    int pos = atomicAdd(&g_cursor[seg], 1);
    g_eidx[pos] = src[e];
}

// ---------------- fused gather-aggregate (one warp per node, fp16 h) ----------
template <int FINAL>
__global__ void __launch_bounds__(256) k_aggregate(int outSlot,
                                                   const float* __restrict__ Wout,
                                                   const float* __restrict__ bout,
                                                   float* __restrict__ out)
{
    int gw = (blockIdx.x * blockDim.x + threadIdx.x) >> 5;
    int lane = threadIdx.x & 31;
    if (gw >= NN) return;

    float a[8];
    {
        uint4 w0 = *(const uint4*)(g_hroot + (size_t)gw * HD + lane * 8);
        const uint32_t* p0 = &w0.x;
#pragma unroll
        for (int q = 0; q < 4; q++) {
            float2 f0 = __half22float2(*(const __half2*)&p0[q]);
            a[q * 2 + 0] = f0.x;
            a[q * 2 + 1] = f0.y;
        }
    }

#pragma unroll
    for (int rel = 0; rel < 2; rel++) {
        int s0 = g_off[rel * NN + gw];
        int s1 = g_off[rel * NN + gw + 1];
        float t[8];
#pragma unroll
        for (int q = 0; q < 8; q++) t[q] = 0.f;
        const __half* hb = g_hrel + (size_t)rel * NN * HD;
        int i = s0;
        for (; i + 1 < s1; i += 2) {
            int sn0 = g_eidx[i], sn1 = g_eidx[i + 1];
            uint4 w0 = *(const uint4*)(hb + (size_t)sn0 * HD + lane * 8);
            uint4 w1 = *(const uint4*)(hb + (size_t)sn1 * HD + lane * 8);
            const uint32_t* p0 = &w0.x;
            const uint32_t* p1 = &w1.x;
#pragma unroll
            for (int q = 0; q < 4; q++) {
                float2 f0 = __half22float2(*(const __half2*)&p0[q]);
                float2 f1 = __half22float2(*(const __half2*)&p1[q]);
                t[q * 2 + 0] += f0.x + f1.x;
                t[q * 2 + 1] += f0.y + f1.y;
            }
        }
        if (i < s1) {
            int sn = g_eidx[i];
            uint4 w0 = *(const uint4*)(hb + (size_t)sn * HD + lane * 8);
            const uint32_t* p0 = &w0.x;
#pragma unroll
            for (int q = 0; q < 4; q++) {
                float2 f0 = __half22float2(*(const __half2*)&p0[q]);
                t[q * 2 + 0] += f0.x;
                t[q * 2 + 1] += f0.y;
            }
        }
        int deg = s1 - s0;
        float inv = 1.f / (float)(deg > 0 ? deg : 1);
#pragma unroll
        for (int q = 0; q < 8; q++) a[q] += t[q] * inv;
    }

    if (FINAL == 0) {
        size_t eoff = (size_t)outSlot * NP * HD + (size_t)gw * HD + lane * 8;
        uint4 hv;
        *(__half2*)&hv.x = __floats2half2_rn(a[0], a[1]);
        *(__half2*)&hv.y = __floats2half2_rn(a[2], a[3]);
        *(__half2*)&hv.z = __floats2half2_rn(a[4], a[5]);
        *(__half2*)&hv.w = __floats2half2_rn(a[6], a[7]);
        *(uint4*)(g_x + eoff) = hv;
    } else {
        float s0 = 0.f, s1 = 0.f;
        int c0 = lane * 8;
#pragma unroll
        for (int q = 0; q < 8; q++) {
            float2 w = *(const float2*)(Wout + (c0 + q) * 2);
            s0 += a[q] * w.x;
            s1 += a[q] * w.y;
        }
#pragma unroll
        for (int o = 16; o; o >>= 1) {
            s0 += __shfl_down_sync(0xFFFFFFFFu, s0, o);
            s1 += __shfl_down_sync(0xFFFFFFFFu, s1, o);
        }
        if (lane == 0) {
            out[(size_t)gw * 2 + 0] = s0 + bout[0];
            out[(size_t)gw * 2 + 1] = s1 + bout[1];
        }
    }
}

// ---------------- launch ------------------------------------------------------
extern "C" void kernel_launch(void* const* d_in, const int* in_sizes, int n_in,
                              void* d_out, int out_size)
{
    const float* des   = (const float*)d_in[0];
    const float* tweet = (const float*)d_in[1];
    const float* nump  = (const float*)d_in[2];
    const float* catp  = (const float*)d_in[3];
    const int*   ei    = (const int*)d_in[4];
    const int*   et    = (const int*)d_in[5];
    const float* w_des = (const float*)d_in[6];
    const float* b_des = (const float*)d_in[7];
    const float* w_tw  = (const float*)d_in[8];
    const float* b_tw  = (const float*)d_in[9];
    const float* w_num = (const float*)d_in[10];
    const float* b_num = (const float*)d_in[11];
    const float* w_cat = (const float*)d_in[12];
    const float* b_cat = (const float*)d_in[13];
    const float* w_in  = (const float*)d_in[14];
    const float* b_in  = (const float*)d_in[15];
    const float* wt1   = (const float*)d_in[16];
    const float* rt1   = (const float*)d_in[17];
    const float* bs1   = (const float*)d_in[18];
    const float* wt2   = (const float*)d_in[19];
    const float* rt2   = (const float*)d_in[20];
    const float* bs2   = (const float*)d_in[21];
    const float* w_out = (const float*)d_in[22];
    const float* b_out = (const float*)d_in[23];
    float* out = (float*)d_out;

    const int* src = ei;
    const int* dst = ei + EE;

    const int SZ128 = 2 * 18432 + 2 * 128 * 144;    // 73728
    const int SZ64  = 2 * 18432 + 2 * 64 * 144;     // 55296
    cudaFuncSetAttribute(k_gemm_mma<128, 1>, cudaFuncAttributeMaxDynamicSharedMemorySize, SZ128);
    cudaFuncSetAttribute(k_gemm_mma<64, 0>,  cudaFuncAttributeMaxDynamicSharedMemorySize, SZ64);

    // side stream: rest-of-weights prep + small projections + CSR chain
    cudaStream_t cs;
    cudaStreamCreateWithFlags(&cs, cudaStreamNonBlocking);
    cudaEvent_t evFork, evW, evJoin;
    cudaEventCreateWithFlags(&evFork, cudaEventDisableTiming);
    cudaEventCreateWithFlags(&evW, cudaEventDisableTiming);
    cudaEventCreateWithFlags(&evJoin, cudaEventDisableTiming);

    cudaEventRecord(evFork, 0);
    cudaStreamWaitEvent(cs, evFork, 0);
    k_wprep_rest<<<dim3((256 * 256 + 255) / 256, 7), 256, 0, cs>>>(w_in, wt1, rt1, wt2, rt2);
    k_projsmall<<<dim3((NN * 64 + 255) / 256, 2), 256, 0, cs>>>(nump, w_num, b_num,
                                                                catp, w_cat, b_cat);
    cudaEventRecord(evW, cs);
    k_zero_cnt<<<(NSEG + 255) / 256, 256, 0, cs>>>();
    k_count<<<(EE + 255) / 256, 256, 0, cs>>>(dst, et);
    k_scan1<<<SCAN_B, 1024, 0, cs>>>();
    k_scan2<<<1, 128, 0, cs>>>();
    k_scan3<<<SCAN_B, 1024, 0, cs>>>();
    k_fill<<<(EE + 255) / 256, 256, 0, cs>>>(src, dst, et);
    cudaEventRecord(evJoin, cs);

    // main chain
    k_wprep768<<<dim3((768 * 64 + 255) / 256, 2), 256>>>(w_des, w_tw);

    const int MB = (NN + 127) / 128;  // 391 row tiles

    k_gemm_mma<64, 0><<<dim3(2, MB), 256, SZ64>>>(des, tweet, 0, 768, NN, 0,
                                                  b_des, b_tw, 1, 64, 0, 1);

    cudaStreamWaitEvent(0, evW, 0);   // OFF_WIN/R1/R2 weights + slot0 cols 128..255 ready
    // x = lrelu(slot0 @ w_in + b_in) -> slot1
    k_gemm_mma<128, 1><<<dim3(2, MB), 256, SZ128>>>(nullptr, nullptr, 0, 256, NN, OFF_WIN,
                                                    b_in, nullptr, 2, 0, 0, 1);

    const int agBl = (NN * 32 + 255) / 256;

    // RGCN layer 1: slot1 -> g_hrel/g_hroot -> slot0
    k_gemm_mma<128, 1><<<dim3(6, MB), 256, SZ128>>>(nullptr, nullptr, 1, 256, NN, OFF_R1,
                                                    bs1, nullptr, 3, 0, 1, 2);
    cudaStreamWaitEvent(0, evJoin, 0);   // CSR must be ready before aggregation
    k_aggregate<0><<<agBl, 256>>>(0, nullptr, nullptr, nullptr);

    // RGCN layer 2: slot0 -> g_hrel/g_hroot -> head logits (fused)
    k_gemm_mma<128, 1><<<dim3(6, MB), 256, SZ128>>>(nullptr, nullptr, 0, 256, NN, OFF_R2,
                                                    bs2, nullptr, 3, 0, 1, 2);
    k_aggregate<1><<<agBl, 256>>>(0, w_out, b_out, out);

    cudaEventDestroy(evFork);
    cudaEventDestroy(evW);
    cudaEventDestroy(evJoin);
    cudaStreamDestroy(cs);
}